// round 5
// baseline (speedup 1.0000x reference)
#include <cuda_runtime.h>
#include <cstdint>

// Problem constants (fixed by the reference setup_inputs)
#define BB 16
#define NN 512
#define DD 256
#define TT 32          // t-tile per block
#define WMAX 40        // max tokens per window (proof bound: 35 at min duration 4)
#define WP 36          // smem pitch (floats) for w[i][tt]; rows 144B -> 16B aligned
#define MARGIN 44      // excluded tokens have arg >= 121 -> fp32 exp underflows to exact 0

// Scratch (allocation-free rule: __device__ globals)
__device__ float g_c[BB * NN];     // gaussian centers
__device__ float g_ir2[BB * NN];   // 1/r^2
__device__ int   g_e[BB * NN];     // inclusive cumsum of durations
__device__ int   g_start[BB * NN]; // segment starts

// ---------------------------------------------------------------------------
// Kernel A: single block, warp-per-batch scan (lane-serial 16 + warp scan)
// ---------------------------------------------------------------------------
__global__ void __launch_bounds__(512)
prep_kernel(const int* __restrict__ dur, const float* __restrict__ ranges) {
    int tid  = threadIdx.x;
    int lane = tid & 31;
    int b    = tid >> 5;           // 16 warps = 16 batches
    int base = b * NN + lane * 16;

    int v[16];
    int s = 0;
    #pragma unroll
    for (int k = 0; k < 16; k++) { v[k] = dur[base + k]; s += v[k]; }

    int p = s;
    #pragma unroll
    for (int o = 1; o < 32; o <<= 1) {
        int u = __shfl_up_sync(0xFFFFFFFFu, p, o);
        if (lane >= o) p += u;
    }
    int run = p - s;               // exclusive prefix

    #pragma unroll
    for (int k = 0; k < 16; k++) {
        int st = run;
        run += v[k];
        int n = base + k;
        g_e[n]     = run;
        g_start[n] = st;
        g_c[n]     = (float)run - 0.5f * (float)v[k];
        float r    = ranges[n];
        g_ir2[n]   = 1.0f / (r * r);
    }
}

// ---------------------------------------------------------------------------
// Kernel B: fused positions + weights + normalized einsum per (batch, 32-t tile)
// ---------------------------------------------------------------------------
__global__ void __launch_bounds__(256)
main_kernel(const float* __restrict__ x,
            float* __restrict__ pos_out,  // [B, T]
            float* __restrict__ out,      // [B, T, D]
            float* __restrict__ weights,  // [B, N, T]
            int T) {
    __shared__ float w[WMAX * WP];        // w[i*WP + tt]
    __shared__ float invw2[TT];
    __shared__ float sc[WMAX], sir[WMAX];
    __shared__ int   sn0, sn1;

    int b    = blockIdx.y;
    int t0   = blockIdx.x * TT;           // multiple of 32
    int ttmx = min(TT, T - t0);
    int tid  = threadIdx.x;
    int lane = tid & 31, warp = tid >> 5;

    const int* eb  = g_e + b * NN;
    const int* stb = g_start + b * NN;

    // Window binary searches (two threads, different warps)
    if (tid == 0) {
        int key = t0 - MARGIN;            // keep tokens with e[n] >= key
        int lo = 0, hi = NN;
        while (lo < hi) { int m = (lo + hi) >> 1; if (eb[m] < key) lo = m + 1; else hi = m; }
        sn0 = lo;
    } else if (tid == 32) {
        int key = t0 + ttmx - 1 + MARGIN; // keep tokens with start[n] <= key
        int lo = 0, hi = NN;
        while (lo < hi) { int m = (lo + hi) >> 1; if (stb[m] <= key) lo = m + 1; else hi = m; }
        sn1 = lo;
    }
    __syncthreads();
    int n0   = sn0;
    int wlen = sn1 - n0;
    if (wlen > WMAX) wlen = WMAX;
    if (wlen < 0)    wlen = 0;

    if (tid < wlen) {
        int n = b * NN + n0 + tid;
        sc[tid]  = g_c[n];
        sir[tid] = g_ir2[n];
    }
    __syncthreads();

    // Phase 1: w[i][tt] = exp(-ir2_i * (t - c_i)^2), window only
    for (int idx = tid; idx < wlen * TT; idx += 256) {
        int i = idx >> 5, tt = idx & 31;
        float dt = (float)(t0 + tt) - sc[i];
        w[i * WP + tt] = __expf(-sir[i] * dt * dt);
    }

    // Positions (warp 0): GLOBAL binary search, exact reference clip semantics
    if (tid < 32 && tid < ttmx) {
        int t = t0 + tid;
        int lo = 0, hi = NN;
        while (lo < hi) { int m = (lo + hi) >> 1; if (eb[m] <= t) lo = m + 1; else hi = m; }
        int seg = min(lo, NN - 1);
        pos_out[b * T + t] = (float)(t - stb[seg]);
    }
    __syncthreads();

    // Phase 2: per-t normalizer (warp handles 4 t's)
    for (int tt = warp; tt < TT; tt += 8) {
        float s = (lane < wlen) ? w[lane * WP + tt] : 0.f;
        if (lane + 32 < wlen) s += w[(lane + 32) * WP + tt];
        #pragma unroll
        for (int o = 16; o; o >>= 1) s += __shfl_xor_sync(0xFFFFFFFFu, s, o);
        if (lane == 0) invw2[tt] = 1.0f / (s + 1e-20f);
    }
    __syncthreads();

    // Phase 3: weights [B,N,T]. t0%32==0, so per-row misalignment = (n*T)&3.
    // Vector body (STG.128) + <=4 boundary scalars per row. Each element is
    // written by exactly one block (its own tile) -> no cross-block races.
    float* wout = weights + b * NN * T;   // int offset (max ~32.2M elems)
    if (ttmx == TT) {
        for (int idx = tid; idx < NN * 8; idx += 256) {
            int n = idx >> 3, q = idx & 7;
            int rowoff = n * T + t0;
            int head = (-rowoff) & 3;
            int nvec = (TT - head) >> 2;  // 7 or 8
            if (q < nvec) {
                int tt = head + q * 4;
                float4 v = make_float4(0.f, 0.f, 0.f, 0.f);
                int i = n - n0;
                if ((unsigned)i < (unsigned)wlen) {
                    const float* wr = &w[i * WP];
                    v.x = wr[tt + 0] * invw2[tt + 0];
                    v.y = wr[tt + 1] * invw2[tt + 1];
                    v.z = wr[tt + 2] * invw2[tt + 2];
                    v.w = wr[tt + 3] * invw2[tt + 3];
                }
                __stcs((float4*)(wout + rowoff + tt), v);
            }
        }
        // boundary scalars (head + tail == 4 when head != 0)
        for (int idx = tid; idx < NN * 4; idx += 256) {
            int n = idx >> 2, k = idx & 3;
            int rowoff = n * T + t0;
            int head = (-rowoff) & 3;
            if (head == 0) continue;
            int nvec = (TT - head) >> 2;
            int tail = TT - head - nvec * 4;
            if (k >= head + tail) continue;
            int tt = (k < head) ? k : (head + nvec * 4 + (k - head));
            int i = n - n0;
            float v = ((unsigned)i < (unsigned)wlen) ? w[i * WP + tt] * invw2[tt] : 0.f;
            __stcs(wout + rowoff + tt, v);
        }
    } else {
        // last partial tile: scalar
        for (int idx = tid; idx < NN * TT; idx += 256) {
            int n = idx >> 5, tt = idx & 31;
            if (tt < ttmx) {
                int i = n - n0;
                float v = ((unsigned)i < (unsigned)wlen) ? w[i * WP + tt] * invw2[tt] : 0.f;
                __stcs(wout + n * T + t0 + tt, v);
            }
        }
    }

    // Phase 4: out[b, t0+tt, :] = invw2[tt] * sum_i w[i][tt] * x[b, n0+i, :]
    // 256 threads: thread = (d-group dg: float4 of d) x (t-group tg: 8 t's).
    // Weight quads are warp-uniform LDS.128 broadcasts. Depth-1 pipeline on i.
    int dg = tid & 63;   // d = dg*4
    int tg = tid >> 6;   // t's = tg*8 .. tg*8+7 (uniform per warp)
    float4 acc[8];
    #pragma unroll
    for (int j = 0; j < 8; j++) acc[j] = make_float4(0.f, 0.f, 0.f, 0.f);

    const float4* xb = (const float4*)(x + b * NN * DD) + dg;
    int wq = tg * 8;

    float4 xv_n, wa_n, wb_n;
    if (wlen > 0) {
        xv_n = xb[n0 * (DD / 4)];
        wa_n = *(const float4*)&w[wq];
        wb_n = *(const float4*)&w[wq + 4];
    }
    for (int i = 0; i < wlen; i++) {
        float4 xv = xv_n, wa = wa_n, wb = wb_n;
        if (i + 1 < wlen) {
            xv_n = xb[(n0 + i + 1) * (DD / 4)];
            wa_n = *(const float4*)&w[(i + 1) * WP + wq];
            wb_n = *(const float4*)&w[(i + 1) * WP + wq + 4];
        }
        float ws[8] = {wa.x, wa.y, wa.z, wa.w, wb.x, wb.y, wb.z, wb.w};
        #pragma unroll
        for (int j = 0; j < 8; j++) {
            acc[j].x += ws[j] * xv.x;
            acc[j].y += ws[j] * xv.y;
            acc[j].z += ws[j] * xv.z;
            acc[j].w += ws[j] * xv.w;
        }
    }

    float* ob = out + b * T * DD + t0 * DD + dg * 4;
    #pragma unroll
    for (int j = 0; j < 8; j++) {
        int tt = tg * 8 + j;
        if (tt < ttmx) {
            float s = invw2[tt];
            float4 v = make_float4(acc[j].x * s, acc[j].y * s,
                                   acc[j].z * s, acc[j].w * s);
            __stcs((float4*)(ob + tt * DD), v);
        }
    }
}

// ---------------------------------------------------------------------------
extern "C" void kernel_launch(void* const* d_in, const int* in_sizes, int n_in,
                              void* d_out, int out_size) {
    const float* x   = (const float*)d_in[0];
    const int*   dur = (const int*)d_in[1];
    const float* rng = (const float*)d_in[2];

    // out = positions[B,T] ++ out[B,T,D] ++ weights[B,N,T], all float32
    int T = out_size / (BB * (1 + DD) + BB * NN);

    float* pos_out = (float*)d_out;
    float* einsum  = pos_out + (size_t)BB * T;
    float* wts     = einsum + (size_t)BB * T * DD;

    prep_kernel<<<1, 512>>>(dur, rng);

    int nTiles = (T + TT - 1) / TT;
    dim3 grid(nTiles, BB);
    main_kernel<<<grid, 256>>>(x, pos_out, einsum, wts, T);
}

// round 6
// speedup vs baseline: 1.9178x; 1.9178x over previous
#include <cuda_runtime.h>
#include <cstdint>

// Problem constants (fixed by the reference setup_inputs)
#define BB 16
#define NN 512
#define DD 256
#define TT 32          // t-tile per block
#define WMAX 36        // max tokens in window (bound: <=31 at min duration 4)
#define P 37           // smem pitch (odd -> conflict-free strided access)
#define MARGIN 44      // excluded tokens have arg >= 121 -> fp32 exp == exact 0

// Scratch (allocation-free rule: __device__ globals)
__device__ float g_c[BB * NN];     // gaussian centers
__device__ float g_ir2[BB * NN];   // 1/r^2
__device__ int   g_e[BB * NN];     // inclusive cumsum of durations
__device__ int   g_start[BB * NN]; // segment starts

// ---------------------------------------------------------------------------
// Kernel A: per-batch inclusive scan + derived per-token params  (R2 verbatim)
// ---------------------------------------------------------------------------
__global__ void __launch_bounds__(NN)
prep_kernel(const int* __restrict__ dur,
            const float* __restrict__ ranges) {
    __shared__ int s[NN];
    __shared__ int part[16];
    int b = blockIdx.x;
    int n = threadIdx.x;
    int lane = n & 31, wid = n >> 5;

    int d = dur[b * NN + n];
    int v = d;
    #pragma unroll
    for (int o = 1; o < 32; o <<= 1) {
        int u = __shfl_up_sync(0xFFFFFFFFu, v, o);
        if (lane >= o) v += u;
    }
    if (lane == 31) part[wid] = v;
    __syncthreads();
    if (wid == 0) {
        int p = (lane < 16) ? part[lane] : 0;
        #pragma unroll
        for (int o = 1; o < 16; o <<= 1) {
            int u = __shfl_up_sync(0xFFFFFFFFu, p, o);
            if (lane >= o) p += u;
        }
        if (lane < 16) part[lane] = p;
    }
    __syncthreads();
    int e = v + (wid ? part[wid - 1] : 0);
    (void)s;

    g_e[b * NN + n]     = e;
    g_start[b * NN + n] = e - d;
    g_c[b * NN + n]     = (float)e - 0.5f * (float)d;
    float r = ranges[b * NN + n];
    g_ir2[b * NN + n]   = 1.0f / (r * r);
}

// ---------------------------------------------------------------------------
// Kernel B: positions (R2 verbatim)
// ---------------------------------------------------------------------------
__global__ void pos_kernel(float* __restrict__ pos_out, int T) {
    int idx = blockIdx.x * blockDim.x + threadIdx.x;
    if (idx >= BB * T) return;
    int b = idx / T;
    int t = idx - b * T;
    const int* e = g_e + b * NN;
    int lo = 0, hi = NN;
    while (lo < hi) {
        int mid = (lo + hi) >> 1;
        if (e[mid] <= t) lo = mid + 1; else hi = mid;
    }
    int seg = min(lo, NN - 1);
    pos_out[idx] = (float)(t - g_start[b * NN + seg]);
}

// ---------------------------------------------------------------------------
// Kernel C: fused weights + normalized einsum (R2, with cheap zero-row stores)
// ---------------------------------------------------------------------------
__global__ void __launch_bounds__(256)
main_kernel(const float* __restrict__ x,
            float* __restrict__ out,      // [B, T, D]
            float* __restrict__ weights,  // [B, N, T]
            int T) {
    __shared__ float w[TT * P];
    __shared__ float invw2[TT];
    __shared__ float sc[WMAX];
    __shared__ float sir[WMAX];
    __shared__ int   sn0, sn1;

    int b    = blockIdx.y;
    int t0   = blockIdx.x * TT;           // multiple of 32
    int ttmx = min(TT, T - t0);
    int tid  = threadIdx.x;
    int lane = tid & 31, warp = tid >> 5;

    const int* eb  = g_e + b * NN;
    const int* stb = g_start + b * NN;

    // Window binary searches (two threads in different warps)
    if (tid == 0) {
        int key = t0 - MARGIN;            // keep tokens with e[n] >= key
        int lo = 0, hi = NN;
        while (lo < hi) { int m = (lo + hi) >> 1; if (eb[m] < key) lo = m + 1; else hi = m; }
        sn0 = lo;
    } else if (tid == 32) {
        int key = t0 + ttmx - 1 + MARGIN; // keep tokens with start[n] <= key
        int lo = 0, hi = NN;
        while (lo < hi) { int m = (lo + hi) >> 1; if (stb[m] <= key) lo = m + 1; else hi = m; }
        sn1 = lo;
    }
    __syncthreads();
    int n0   = sn0;
    int wlen = sn1 - n0;
    if (wlen > WMAX) wlen = WMAX;
    if (wlen < 0)    wlen = 0;

    if (tid < wlen) {
        sc[tid]  = g_c[b * NN + n0 + tid];
        sir[tid] = g_ir2[b * NN + n0 + tid];
    }
    __syncthreads();

    // Phase 1: w[tt][i] = exp(-ir2 * (t - c)^2) for the window only
    for (int idx = tid; idx < wlen * TT; idx += 256) {
        int i = idx >> 5, tt = idx & 31;
        float dt = (float)(t0 + tt) - sc[i];
        w[tt * P + i] = __expf(-sir[i] * dt * dt);
    }
    __syncthreads();

    // Phase 2: per-t normalizer
    for (int tt = warp; tt < TT; tt += 8) {
        float s = (lane < wlen) ? w[tt * P + lane] : 0.f;
        if (lane + 32 < wlen) s += w[tt * P + lane + 32];
        #pragma unroll
        for (int o = 16; o; o >>= 1) s += __shfl_xor_sync(0xFFFFFFFFu, s, o);
        if (lane == 0) invw2[tt] = 1.0f / (s + 1e-20f);
    }
    __syncthreads();

    // Phase 3a: in-window rows (<= WMAX*32 elements) — scalar with data
    float* wout = weights + (size_t)b * NN * T;
    for (int idx = tid; idx < wlen * TT; idx += 256) {
        int i = idx >> 5, tt = idx & 31;
        if (tt < ttmx) {
            int n = n0 + i;
            __stcs(wout + (size_t)n * T + t0 + tt, w[tt * P + i] * invw2[tt]);
        }
    }

    // Phase 3b: zero rows — aligned STG.128 zeros for any T, 8 slots/row.
    // head = misalignment of this row segment; 7 (or 8) float4 + <=4 scalars.
    if (ttmx == TT) {
        const float4 z4 = make_float4(0.f, 0.f, 0.f, 0.f);
        for (int idx = tid; idx < NN * 8; idx += 256) {
            int n = idx >> 3, q = idx & 7;
            if ((unsigned)(n - n0) < (unsigned)wlen) continue;
            int rowoff = n * T + t0;          // < 2^25, int-safe
            int head = (-rowoff) & 3;
            if (head == 0) {
                __stcs((float4*)(wout + rowoff) + q, z4);
            } else if (q < 7) {
                __stcs((float4*)(wout + rowoff + head) + q, z4);
            } else {
                #pragma unroll
                for (int k = 0; k < 3; k++)
                    if (k < head) __stcs(wout + rowoff + k, 0.f);
                int tail = 4 - head;
                #pragma unroll
                for (int k = 0; k < 3; k++)
                    if (k < tail) __stcs(wout + rowoff + head + 28 + k, 0.f);
            }
        }
    } else {
        for (int idx = tid; idx < NN * TT; idx += 256) {
            int n = idx >> 5, tt = idx & 31;
            if (tt < ttmx && (unsigned)(n - n0) >= (unsigned)wlen)
                __stcs(wout + (size_t)n * T + t0 + tt, 0.f);
        }
    }

    // Phase 4: out[b, t0:t0+32, :]  (R2 verbatim)
    int dg = tid & 63;   // d-group (d = dg*4)
    int tg = tid >> 6;   // t-group (t's = tg*8 .. tg*8+7), uniform per warp
    float4 acc[8];
    #pragma unroll
    for (int j = 0; j < 8; j++) acc[j] = make_float4(0.f, 0.f, 0.f, 0.f);

    const float4* xb = (const float4*)(x + (size_t)b * NN * DD) + dg;
    for (int i = 0; i < wlen; i++) {
        float4 xv = xb[(size_t)(n0 + i) * (DD / 4)];
        #pragma unroll
        for (int j = 0; j < 8; j++) {
            float wv = w[(tg * 8 + j) * P + i];  // warp-uniform broadcast
            acc[j].x += wv * xv.x;
            acc[j].y += wv * xv.y;
            acc[j].z += wv * xv.z;
            acc[j].w += wv * xv.w;
        }
    }

    float* ob = out + (size_t)b * T * DD + (size_t)t0 * DD + dg * 4;
    #pragma unroll
    for (int j = 0; j < 8; j++) {
        int tt = tg * 8 + j;
        if (tt < ttmx) {
            float s = invw2[tt];
            float4 v = make_float4(acc[j].x * s, acc[j].y * s,
                                   acc[j].z * s, acc[j].w * s);
            __stcs((float4*)(ob + (size_t)tt * DD), v);
        }
    }
}

// ---------------------------------------------------------------------------
extern "C" void kernel_launch(void* const* d_in, const int* in_sizes, int n_in,
                              void* d_out, int out_size) {
    const float* x   = (const float*)d_in[0];
    const int*   dur = (const int*)d_in[1];
    const float* rng = (const float*)d_in[2];

    // out = positions[B,T] ++ out[B,T,D] ++ weights[B,N,T], all float32
    int T = out_size / (BB * (1 + DD) + BB * NN);

    float* pos_out = (float*)d_out;
    float* einsum  = pos_out + (size_t)BB * T;
    float* wts     = einsum + (size_t)BB * T * DD;

    prep_kernel<<<BB, NN>>>(dur, rng);

    int posThreads = BB * T;
    pos_kernel<<<(posThreads + 255) / 256, 256>>>(pos_out, T);

    int nTiles = (T + TT - 1) / TT;
    dim3 grid(nTiles, BB);
    main_kernel<<<grid, 256>>>(x, pos_out + (size_t)BB * T, wts, T);
}

// round 7
// speedup vs baseline: 2.3092x; 1.2041x over previous
#include <cuda_runtime.h>
#include <cstdint>

// Problem constants (fixed by the reference setup_inputs)
#define BB 16
#define NN 512
#define DD 256
#define TT 32          // t-tile per block
#define WMAX 36        // max tokens in window (bound: <=31 at min duration 4)
#define WP 36          // pitch (floats) for w[i][tt]; rows 144B -> 16B aligned
#define MARGIN 44      // excluded tokens have arg >= 121 -> fp32 exp == exact 0

// Scratch (allocation-free rule: __device__ globals)
__device__ float g_c[BB * NN];     // gaussian centers
__device__ float g_ir2[BB * NN];   // 1/r^2
__device__ int   g_e[BB * NN];     // inclusive cumsum of durations
__device__ int   g_start[BB * NN]; // segment starts

// ---------------------------------------------------------------------------
// Kernel A: per-batch warp-scan cumsum + derived params + fused positions
// (63.1us version, verbatim)
// ---------------------------------------------------------------------------
__global__ void __launch_bounds__(NN)
prep_kernel(const int* __restrict__ dur,
            const float* __restrict__ ranges,
            float* __restrict__ pos_out, int T) {
    __shared__ int se[NN];
    __shared__ int sst[NN];
    __shared__ int part[16];
    int b = blockIdx.x;
    int n = threadIdx.x;
    int lane = n & 31, wid = n >> 5;

    int d = dur[b * NN + n];
    int v = d;
    #pragma unroll
    for (int o = 1; o < 32; o <<= 1) {
        int u = __shfl_up_sync(0xFFFFFFFFu, v, o);
        if (lane >= o) v += u;
    }
    if (lane == 31) part[wid] = v;
    __syncthreads();
    if (wid == 0) {
        int p = (lane < 16) ? part[lane] : 0;
        #pragma unroll
        for (int o = 1; o < 16; o <<= 1) {
            int u = __shfl_up_sync(0xFFFFFFFFu, p, o);
            if (lane >= o) p += u;
        }
        if (lane < 16) part[lane] = p;
    }
    __syncthreads();
    int e = v + (wid ? part[wid - 1] : 0);

    se[n]  = e;
    sst[n] = e - d;
    g_e[b * NN + n]     = e;
    g_start[b * NN + n] = e - d;
    g_c[b * NN + n]     = (float)e - 0.5f * (float)d;
    float r = ranges[b * NN + n];
    g_ir2[b * NN + n]   = 1.0f / (r * r);
    __syncthreads();

    // positions[b,t] = t - start[clip(searchsorted(e, t, 'right'))]
    for (int t = n; t < T; t += NN) {
        int lo = 0, hi = NN;
        while (lo < hi) {
            int m = (lo + hi) >> 1;
            if (se[m] <= t) lo = m + 1; else hi = m;
        }
        int seg = min(lo, NN - 1);
        pos_out[b * T + t] = (float)(t - sst[seg]);
    }
}

// ---------------------------------------------------------------------------
// Kernel B: fused weights + normalized einsum (63.1us version; ONLY change:
// tile layout transposed to w[i][tt] so tile reads are LDS.128)
// ---------------------------------------------------------------------------
__global__ void __launch_bounds__(256)
main_kernel(const float* __restrict__ x,
            float* __restrict__ out,      // [B, T, D]
            float* __restrict__ weights,  // [B, N, T]
            int T) {
    __shared__ __align__(16) float w[WMAX * WP];   // w[i*WP + tt]
    __shared__ __align__(16) float invw2[TT];
    __shared__ float sc[WMAX];
    __shared__ float sir[WMAX];
    __shared__ int   sn0, sn1;

    int b    = blockIdx.y;
    int t0   = blockIdx.x * TT;
    int ttmx = min(TT, T - t0);
    int tid  = threadIdx.x;
    int lane = tid & 31, warp = tid >> 5;

    const int* eb  = g_e + b * NN;
    const int* stb = g_start + b * NN;

    // Window binary searches (two threads in different warps)
    if (tid == 0) {
        int key = t0 - MARGIN;            // keep tokens with e[n] >= key
        int lo = 0, hi = NN;
        while (lo < hi) { int m = (lo + hi) >> 1; if (eb[m] < key) lo = m + 1; else hi = m; }
        sn0 = lo;
    } else if (tid == 32) {
        int key = t0 + ttmx - 1 + MARGIN; // keep tokens with start[n] <= key
        int lo = 0, hi = NN;
        while (lo < hi) { int m = (lo + hi) >> 1; if (stb[m] <= key) lo = m + 1; else hi = m; }
        sn1 = lo;
    }
    __syncthreads();
    int n0   = sn0;
    int wlen = sn1 - n0;
    if (wlen > WMAX) wlen = WMAX;
    if (wlen < 0)    wlen = 0;

    if (tid < wlen) {
        sc[tid]  = g_c[b * NN + n0 + tid];
        sir[tid] = g_ir2[b * NN + n0 + tid];
    }
    __syncthreads();

    // Phase 1: w[i][tt] = exp(-ir2 * (t - c)^2) for the window only
    for (int idx = tid; idx < wlen * TT; idx += 256) {
        int i = idx >> 5, tt = idx & 31;
        float dt = (float)(t0 + tt) - sc[i];
        w[i * WP + tt] = __expf(-sir[i] * dt * dt);
    }
    __syncthreads();

    // Phase 2: per-t normalizer (stride-WP reads; tiny phase, conflicts ok)
    for (int tt = warp; tt < TT; tt += 8) {
        float s = (lane < wlen) ? w[lane * WP + tt] : 0.f;
        if (lane + 32 < wlen) s += w[(lane + 32) * WP + tt];
        #pragma unroll
        for (int o = 16; o; o >>= 1) s += __shfl_xor_sync(0xFFFFFFFFu, s, o);
        if (lane == 0) invw2[tt] = 1.0f / (s + 1e-20f);
    }
    __syncthreads();

    // Phase 3: weights [B,N,T] — mostly-zero rows, streaming float4 stores
    float* wout = weights + (size_t)b * NN * T + t0;
    if (ttmx == TT && (T & 3) == 0) {
        // vector path: thread -> (row n, quad q of 4 t's)
        for (int idx = tid; idx < NN * 8; idx += 256) {
            int n = idx >> 3, q = idx & 7;
            float4 v = make_float4(0.f, 0.f, 0.f, 0.f);
            int i = n - n0;
            if ((unsigned)i < (unsigned)wlen) {
                float4 wv = *(const float4*)&w[i * WP + q * 4];
                float4 iv = *(const float4*)&invw2[q * 4];
                v = make_float4(wv.x * iv.x, wv.y * iv.y, wv.z * iv.z, wv.w * iv.w);
            }
            __stcs(((float4*)(wout + (size_t)n * T)) + q, v);
        }
    } else {
        for (int idx = tid; idx < NN * TT; idx += 256) {
            int n = idx >> 5, tt = idx & 31;
            if (tt < ttmx) {
                int i = n - n0;
                float v = ((unsigned)i < (unsigned)wlen) ? w[i * WP + tt] * invw2[tt] : 0.f;
                __stcs(wout + (size_t)n * T + tt, v);
            }
        }
    }

    // Phase 4: out[b, t0:t0+32, :] = sum_i w[i][tt]*invw2[tt] * x[b,n0+i,:]
    // Thread: 4 consecutive d (float4) x 8 t's -> 32 accumulators.
    // Weight reads: 2 warp-uniform LDS.128 per i (tg uniform per warp).
    int dg = tid & 63;   // d-group (d = dg*4)
    int tg = tid >> 6;   // t-group (t's = tg*8 .. tg*8+7)
    float4 acc[8];
    #pragma unroll
    for (int j = 0; j < 8; j++) acc[j] = make_float4(0.f, 0.f, 0.f, 0.f);

    const float4* xb = (const float4*)(x + (size_t)b * NN * DD) + dg;
    for (int i = 0; i < wlen; i++) {
        float4 xv = xb[(size_t)(n0 + i) * (DD / 4)];
        const float4* wrow = (const float4*)&w[i * WP] + tg * 2;
        float4 wa = wrow[0];
        float4 wb = wrow[1];
        acc[0].x += wa.x * xv.x; acc[0].y += wa.x * xv.y; acc[0].z += wa.x * xv.z; acc[0].w += wa.x * xv.w;
        acc[1].x += wa.y * xv.x; acc[1].y += wa.y * xv.y; acc[1].z += wa.y * xv.z; acc[1].w += wa.y * xv.w;
        acc[2].x += wa.z * xv.x; acc[2].y += wa.z * xv.y; acc[2].z += wa.z * xv.z; acc[2].w += wa.z * xv.w;
        acc[3].x += wa.w * xv.x; acc[3].y += wa.w * xv.y; acc[3].z += wa.w * xv.z; acc[3].w += wa.w * xv.w;
        acc[4].x += wb.x * xv.x; acc[4].y += wb.x * xv.y; acc[4].z += wb.x * xv.z; acc[4].w += wb.x * xv.w;
        acc[5].x += wb.y * xv.x; acc[5].y += wb.y * xv.y; acc[5].z += wb.y * xv.z; acc[5].w += wb.y * xv.w;
        acc[6].x += wb.z * xv.x; acc[6].y += wb.z * xv.y; acc[6].z += wb.z * xv.z; acc[6].w += wb.z * xv.w;
        acc[7].x += wb.w * xv.x; acc[7].y += wb.w * xv.y; acc[7].z += wb.w * xv.z; acc[7].w += wb.w * xv.w;
    }

    float* ob = out + (size_t)b * T * DD + (size_t)t0 * DD + dg * 4;
    #pragma unroll
    for (int j = 0; j < 8; j++) {
        int tt = tg * 8 + j;
        if (tt < ttmx) {
            float s = invw2[tt];
            float4 v = make_float4(acc[j].x * s, acc[j].y * s,
                                   acc[j].z * s, acc[j].w * s);
            __stcs((float4*)(ob + (size_t)tt * DD), v);
        }
    }
}

// ---------------------------------------------------------------------------
extern "C" void kernel_launch(void* const* d_in, const int* in_sizes, int n_in,
                              void* d_out, int out_size) {
    const float* x   = (const float*)d_in[0];
    const int*   dur = (const int*)d_in[1];
    const float* rng = (const float*)d_in[2];

    // out = positions[B,T] ++ out[B,T,D] ++ weights[B,N,T], all float32
    int T = out_size / (BB * (1 + DD) + BB * NN);

    float* pos_out = (float*)d_out;
    float* einsum  = pos_out + (size_t)BB * T;
    float* wts     = einsum + (size_t)BB * T * DD;

    prep_kernel<<<BB, NN>>>(dur, rng, pos_out, T);

    int nTiles = (T + TT - 1) / TT;
    dim3 grid(nTiles, BB);
    main_kernel<<<grid, 256>>>(x, einsum, wts, T);
}